// round 9
// baseline (speedup 1.0000x reference)
#include <cuda_runtime.h>
#include <cuda_bf16.h>
#include <cstdint>
#include <math.h>

// ---------------- problem constants ----------------
constexpr int T_TOK = 401408;      // 8*224*224 tokens (= 8192 windows * 49)

// ---------------- scratch (device globals: no cudaMalloc allowed) ----------------
__device__ __align__(16) __nv_bfloat16 g_qkv [(size_t)T_TOK * 576];
__device__ __align__(16) __nv_bfloat16 g_attn[(size_t)T_TOK * 192];
__device__ __align__(16) __nv_bfloat16 g_wqkv[192 * 576];
__device__ __align__(16) __nv_bfloat16 g_wproj[192 * 192];
__device__ __align__(16) __nv_bfloat16 g_w1  [192 * 768];
__device__ __align__(16) __nv_bfloat16 g_w2  [768 * 192];

// ---------------- row mapping: window row -> image row ----------------
__device__ __forceinline__ int maprow(int r) {
    int w  = r / 49;
    int t  = r - w * 49;
    int wb = w >> 10;
    int wi = w & 1023;
    int wh = wi >> 5;
    int ww = wi & 31;
    int th = t / 7;
    int tw = t - th * 7;
    int h  = wh * 7 + th + 3; if (h  >= 224) h  -= 224;
    int wc = ww * 7 + tw + 3; if (wc >= 224) wc -= 224;
    return wb * 50176 + h * 224 + wc;
}

// ---------------- tiny helpers ----------------
__global__ void convert_kernel(const float* __restrict__ s, __nv_bfloat16* __restrict__ d, int n) {
    int i = blockIdx.x * blockDim.x + threadIdx.x;
    if (i < n) d[i] = __float2bfloat16(s[i]);
}

__device__ __forceinline__ void cp16(uint32_t smaddr, const void* g) {
    asm volatile("cp.async.cg.shared.global [%0],[%1],16;\n" :: "r"(smaddr), "l"(g));
}
__device__ __forceinline__ void cp_commit() { asm volatile("cp.async.commit_group;\n"); }
template <int N> __device__ __forceinline__ void cp_wait() {
    asm volatile("cp.async.wait_group %0;\n" :: "n"(N));
}
__device__ __forceinline__ void ldm_x4(uint32_t& r0, uint32_t& r1, uint32_t& r2, uint32_t& r3,
                                       uint32_t addr) {
    asm volatile("ldmatrix.sync.aligned.m8n8.x4.shared.b16 {%0,%1,%2,%3},[%4];\n"
                 : "=r"(r0), "=r"(r1), "=r"(r2), "=r"(r3) : "r"(addr));
}
__device__ __forceinline__ void ldm_x2(uint32_t& r0, uint32_t& r1, uint32_t addr) {
    asm volatile("ldmatrix.sync.aligned.m8n8.x2.shared.b16 {%0,%1},[%2];\n"
                 : "=r"(r0), "=r"(r1) : "r"(addr));
}
__device__ __forceinline__ void ldm_x2t(uint32_t& r0, uint32_t& r1, uint32_t addr) {
    asm volatile("ldmatrix.sync.aligned.m8n8.x2.trans.shared.b16 {%0,%1},[%2];\n"
                 : "=r"(r0), "=r"(r1) : "r"(addr));
}
__device__ __forceinline__ void mma_bf16(float& c0, float& c1, float& c2, float& c3,
                                         uint32_t a0, uint32_t a1, uint32_t a2, uint32_t a3,
                                         uint32_t b0, uint32_t b1) {
    asm volatile(
        "mma.sync.aligned.m16n8k16.row.col.f32.bf16.bf16.f32 "
        "{%0,%1,%2,%3},{%4,%5,%6,%7},{%8,%9},{%0,%1,%2,%3};\n"
        : "+f"(c0), "+f"(c1), "+f"(c2), "+f"(c3)
        : "r"(a0), "r"(a1), "r"(a2), "r"(a3), "r"(b0), "r"(b1));
}
__device__ __forceinline__ float gelu_exact(float v) {
    return 0.5f * v * (1.f + erff(v * 0.7071067811865476f));
}
__device__ __forceinline__ uint32_t packbf(float a, float b) {
    __nv_bfloat162 t = __floats2bfloat162_rn(a, b);
    return *reinterpret_cast<uint32_t*>(&t);
}

// ================= fused LN1 + QKV GEMM (M-tile 128, K=192, N=576) =================
constexpr int AS_STR = 200;
constexpr int BS_STR = 72;
constexpr int SMEM_QKV = (128 * AS_STR + 2 * 192 * BS_STR) * 2;  // 106496

__global__ void __launch_bounds__(256, 2) gemmQKV_kernel(const float* __restrict__ x,
                                                         const float* __restrict__ n1w,
                                                         const float* __restrict__ n1b,
                                                         const __nv_bfloat16* __restrict__ B,
                                                         const float* __restrict__ bias,
                                                         __nv_bfloat16* __restrict__ outB) {
    extern __shared__ __align__(16) __nv_bfloat16 smem[];
    __nv_bfloat16* As = smem;
    const uint32_t sA = (uint32_t)__cvta_generic_to_shared(As);
    const uint32_t sB = sA + 128 * AS_STR * 2;
    const int tid = threadIdx.x;
    const int m0 = blockIdx.x * 128;
    const int warp = tid >> 5, lane = tid & 31;

    // issue B tile 0 (flies under the LN phase)
#pragma unroll
    for (int i = 0; i < 6; i++) {
        int c = tid + 256 * i;
        int k = c >> 3, nn = (c & 7) * 8;
        cp16(sB + (k * BS_STR + nn) * 2, B + (size_t)k * 576 + nn);
    }
    cp_commit();

    // LN1 gather: each warp normalizes 16 rows into As
    for (int rr = 0; rr < 16; rr++) {
        int rl = warp * 16 + rr;
        const float* p = x + (size_t)maprow(m0 + rl) * 192;
        float v[6];
        float s = 0.f, s2 = 0.f;
#pragma unroll
        for (int k = 0; k < 6; k++) {
            v[k] = p[lane + 32 * k];
            s += v[k];
            s2 = fmaf(v[k], v[k], s2);
        }
#pragma unroll
        for (int o = 16; o > 0; o >>= 1) {
            s  += __shfl_xor_sync(0xffffffffu, s,  o);
            s2 += __shfl_xor_sync(0xffffffffu, s2, o);
        }
        float mean = s * (1.f / 192.f);
        float var  = s2 * (1.f / 192.f) - mean * mean;
        float rstd = rsqrtf(var + 1e-5f);
#pragma unroll
        for (int k = 0; k < 6; k++) {
            int c = lane + 32 * k;
            As[rl * AS_STR + c] = __float2bfloat16((v[k] - mean) * rstd * n1w[c] + n1b[c]);
        }
    }
    __syncthreads();

    const int wm = warp >> 1, wn = warp & 1;
    const int gid = lane >> 2, tig = lane & 3;
    const int l15 = lane & 15;
    const uint32_t BUFB = 192 * BS_STR * 2;
    uint32_t bufOff = 0;

    for (int nt = 0; nt < 9; nt++) {
        cp_wait<0>();
        __syncthreads();
        if (nt + 1 < 9) {
            uint32_t other = BUFB - bufOff;
            const __nv_bfloat16* Bg = B + (nt + 1) * 64;
#pragma unroll
            for (int i = 0; i < 6; i++) {
                int c = tid + 256 * i;
                int k = c >> 3, nn = (c & 7) * 8;
                cp16(sB + other + (k * BS_STR + nn) * 2, Bg + (size_t)k * 576 + nn);
            }
            cp_commit();
        }

        float acc[2][4][4] = {};
#pragma unroll
        for (int kb = 0; kb < 192; kb += 16) {
            uint32_t a[2][4];
#pragma unroll
            for (int mi = 0; mi < 2; mi++)
                ldm_x4(a[mi][0], a[mi][1], a[mi][2], a[mi][3],
                       sA + ((wm * 32 + mi * 16 + l15) * AS_STR + kb + (lane >> 4) * 8) * 2);
            uint32_t bfr[4][2];
#pragma unroll
            for (int ni = 0; ni < 4; ni++)
                ldm_x2t(bfr[ni][0], bfr[ni][1],
                        sB + bufOff + ((kb + l15) * BS_STR + wn * 32 + ni * 8) * 2);
#pragma unroll
            for (int mi = 0; mi < 2; mi++)
#pragma unroll
                for (int ni = 0; ni < 4; ni++)
                    mma_bf16(acc[mi][ni][0], acc[mi][ni][1], acc[mi][ni][2], acc[mi][ni][3],
                             a[mi][0], a[mi][1], a[mi][2], a[mi][3],
                             bfr[ni][0], bfr[ni][1]);
        }

#pragma unroll
        for (int mi = 0; mi < 2; mi++) {
#pragma unroll
            for (int ni = 0; ni < 4; ni++) {
                int colg = nt * 64 + wn * 32 + ni * 8 + tig * 2;
                float b0 = __ldg(bias + colg), b1 = __ldg(bias + colg + 1);
#pragma unroll
                for (int hh = 0; hh < 2; hh++) {
                    int row = m0 + wm * 32 + mi * 16 + gid + hh * 8;
                    uint32_t pk = packbf(acc[mi][ni][hh * 2] + b0, acc[mi][ni][hh * 2 + 1] + b1);
                    *reinterpret_cast<uint32_t*>(outB + (size_t)row * 576 + colg) = pk;
                }
            }
        }
        bufOff = BUFB - bufOff;
    }
}

// ================= MEGA: proj + resid + LN2 + MLP1(GELU) + MLP2 + resid =================
// 64 rows per CTA, 256 threads. hidden never touches gmem.
constexpr int MG_AS   = 0;                         // As: 64 x 200 bf16 = 25600 B
constexpr int MG_BS   = 25600;                     // B region: 55296 B
constexpr int MG_R4   = 25600 + 55296;             // 80896; R4: 99328 B (Sout fp32 / hid bf16)
constexpr int MG_SMEM = MG_R4 + 99328;             // 180224 B
constexpr int S4_STR  = 196;                       // fp32 stride for Sout
constexpr int H_STR   = 776;                       // bf16 stride for hidden (768+8)

__global__ void __launch_bounds__(256, 1) mega_kernel(
    const __nv_bfloat16* __restrict__ attnb, const __nv_bfloat16* __restrict__ wproj,
    const float* __restrict__ proj_b, const float* __restrict__ x,
    const float* __restrict__ n2w, const float* __restrict__ n2b,
    const __nv_bfloat16* __restrict__ w1, const float* __restrict__ b1,
    const __nv_bfloat16* __restrict__ w2, const float* __restrict__ b2,
    float* __restrict__ out) {
    extern __shared__ __align__(16) unsigned char sm[];
    __nv_bfloat16* As = reinterpret_cast<__nv_bfloat16*>(sm);
    float* S4 = reinterpret_cast<float*>(sm + MG_R4);
    const uint32_t sA = (uint32_t)__cvta_generic_to_shared(sm);
    const uint32_t sB = sA + MG_BS;
    const uint32_t sH = sA + MG_R4;
    const int tid = threadIdx.x;
    const int m0 = blockIdx.x * 64;
    const int warp = tid >> 5, lane = tid & 31;
    const int wm = warp >> 2, wn = warp & 3;
    const int gid = lane >> 2, tig = lane & 3;
    const int l15 = lane & 15;

    // load A tile (64 x 192 from attnb)
#pragma unroll
    for (int i = 0; i < 6; i++) {
        int c = tid + 256 * i;
        int r = c / 24, co = (c % 24) * 8;
        cp16(sA + (r * AS_STR + co) * 2, attnb + (size_t)(m0 + r) * 192 + co);
    }
    cp_commit();
    // proj B tile 0
#pragma unroll
    for (int i = 0; i < 6; i++) {
        int c = tid + 256 * i;
        int k = c >> 3, nn = (c & 7) * 8;
        cp16(sB + (k * BS_STR + nn) * 2, wproj + (size_t)k * 192 + nn);
    }
    cp_commit();

    const uint32_t BUFB = 192 * BS_STR * 2;
    uint32_t bo = 0;

    // ---- Phase 1: proj (NT=3), epilogue: +bias +resid -> out gmem & S4 smem ----
    for (int nt = 0; nt < 3; nt++) {
        cp_wait<0>();
        __syncthreads();
        if (nt + 1 < 3) {
            uint32_t other = BUFB - bo;
            const __nv_bfloat16* Bg = wproj + (nt + 1) * 64;
#pragma unroll
            for (int i = 0; i < 6; i++) {
                int c = tid + 256 * i;
                int k = c >> 3, nn = (c & 7) * 8;
                cp16(sB + other + (k * BS_STR + nn) * 2, Bg + (size_t)k * 192 + nn);
            }
            cp_commit();
        }
        float acc[2][2][4] = {};
#pragma unroll
        for (int kb = 0; kb < 192; kb += 16) {
            uint32_t a[2][4];
#pragma unroll
            for (int mi = 0; mi < 2; mi++)
                ldm_x4(a[mi][0], a[mi][1], a[mi][2], a[mi][3],
                       sA + ((wm * 32 + mi * 16 + l15) * AS_STR + kb + (lane >> 4) * 8) * 2);
            uint32_t bfr[2][2];
#pragma unroll
            for (int ni = 0; ni < 2; ni++)
                ldm_x2t(bfr[ni][0], bfr[ni][1],
                        sB + bo + ((kb + l15) * BS_STR + wn * 16 + ni * 8) * 2);
#pragma unroll
            for (int mi = 0; mi < 2; mi++)
#pragma unroll
                for (int ni = 0; ni < 2; ni++)
                    mma_bf16(acc[mi][ni][0], acc[mi][ni][1], acc[mi][ni][2], acc[mi][ni][3],
                             a[mi][0], a[mi][1], a[mi][2], a[mi][3],
                             bfr[ni][0], bfr[ni][1]);
        }
#pragma unroll
        for (int mi = 0; mi < 2; mi++) {
#pragma unroll
            for (int ni = 0; ni < 2; ni++) {
                int colg = nt * 64 + wn * 16 + ni * 8 + tig * 2;
                float pb0 = __ldg(proj_b + colg), pb1 = __ldg(proj_b + colg + 1);
#pragma unroll
                for (int hh = 0; hh < 2; hh++) {
                    int row = wm * 32 + mi * 16 + gid + hh * 8;
                    int yr = maprow(m0 + row);
                    float2 xr = *reinterpret_cast<const float2*>(x + (size_t)yr * 192 + colg);
                    float v0 = acc[mi][ni][hh * 2] + pb0 + xr.x;
                    float v1 = acc[mi][ni][hh * 2 + 1] + pb1 + xr.y;
                    float2 o; o.x = v0; o.y = v1;
                    *reinterpret_cast<float2*>(out + (size_t)yr * 192 + colg) = o;
                    *reinterpret_cast<float2*>(&S4[row * S4_STR + colg]) = o;
                }
            }
        }
        bo = BUFB - bo;
    }
    __syncthreads();

    // ---- Phase 2: LN2 on S4 -> normalized bf16 into As ----
#pragma unroll
    for (int k = 0; k < 8; k++) {
        int r = warp * 8 + k;
        float v[6];
        float s = 0.f, s2 = 0.f;
#pragma unroll
        for (int j = 0; j < 6; j++) {
            v[j] = S4[r * S4_STR + lane + 32 * j];
            s += v[j];
            s2 = fmaf(v[j], v[j], s2);
        }
#pragma unroll
        for (int o = 16; o > 0; o >>= 1) {
            s  += __shfl_xor_sync(0xffffffffu, s,  o);
            s2 += __shfl_xor_sync(0xffffffffu, s2, o);
        }
        float mean = s * (1.f / 192.f);
        float var  = s2 * (1.f / 192.f) - mean * mean;
        float rstd = rsqrtf(var + 1e-5f);
#pragma unroll
        for (int j = 0; j < 6; j++) {
            int c = lane + 32 * j;
            As[r * AS_STR + c] = __float2bfloat16((v[j] - mean) * rstd * n2w[c] + n2b[c]);
        }
    }
    // issue mlp1 B tile 0 (overlap with tail of LN)
#pragma unroll
    for (int i = 0; i < 6; i++) {
        int c = tid + 256 * i;
        int k = c >> 3, nn = (c & 7) * 8;
        cp16(sB + (k * BS_STR + nn) * 2, w1 + (size_t)k * 768 + nn);
    }
    cp_commit();
    bo = 0;
    __syncthreads();

    // ---- Phase 3: MLP1 (NT=12) + GELU -> hidden in smem ----
    for (int nt = 0; nt < 12; nt++) {
        cp_wait<0>();
        __syncthreads();
        if (nt + 1 < 12) {
            uint32_t other = BUFB - bo;
            const __nv_bfloat16* Bg = w1 + (nt + 1) * 64;
#pragma unroll
            for (int i = 0; i < 6; i++) {
                int c = tid + 256 * i;
                int k = c >> 3, nn = (c & 7) * 8;
                cp16(sB + other + (k * BS_STR + nn) * 2, Bg + (size_t)k * 768 + nn);
            }
            cp_commit();
        }
        float acc[2][2][4] = {};
#pragma unroll
        for (int kb = 0; kb < 192; kb += 16) {
            uint32_t a[2][4];
#pragma unroll
            for (int mi = 0; mi < 2; mi++)
                ldm_x4(a[mi][0], a[mi][1], a[mi][2], a[mi][3],
                       sA + ((wm * 32 + mi * 16 + l15) * AS_STR + kb + (lane >> 4) * 8) * 2);
            uint32_t bfr[2][2];
#pragma unroll
            for (int ni = 0; ni < 2; ni++)
                ldm_x2t(bfr[ni][0], bfr[ni][1],
                        sB + bo + ((kb + l15) * BS_STR + wn * 16 + ni * 8) * 2);
#pragma unroll
            for (int mi = 0; mi < 2; mi++)
#pragma unroll
                for (int ni = 0; ni < 2; ni++)
                    mma_bf16(acc[mi][ni][0], acc[mi][ni][1], acc[mi][ni][2], acc[mi][ni][3],
                             a[mi][0], a[mi][1], a[mi][2], a[mi][3],
                             bfr[ni][0], bfr[ni][1]);
        }
        __nv_bfloat16* H = reinterpret_cast<__nv_bfloat16*>(sm + MG_R4);
#pragma unroll
        for (int mi = 0; mi < 2; mi++) {
#pragma unroll
            for (int ni = 0; ni < 2; ni++) {
                int colg = nt * 64 + wn * 16 + ni * 8 + tig * 2;
                float hb0 = __ldg(b1 + colg), hb1 = __ldg(b1 + colg + 1);
#pragma unroll
                for (int hh = 0; hh < 2; hh++) {
                    int row = wm * 32 + mi * 16 + gid + hh * 8;
                    float v0 = gelu_exact(acc[mi][ni][hh * 2] + hb0);
                    float v1 = gelu_exact(acc[mi][ni][hh * 2 + 1] + hb1);
                    uint32_t pk = packbf(v0, v1);
                    *reinterpret_cast<uint32_t*>(&H[row * H_STR + colg]) = pk;
                }
            }
        }
        bo = BUFB - bo;
    }

    // issue first two w2 chunks
    auto issueW2 = [&](int kc, uint32_t off) {
        int kk = kc * 32;
#pragma unroll
        for (int i = 0; i < 3; i++) {
            int c = tid + 256 * i;
            int k = c / 24, nn = (c % 24) * 8;
            cp16(sB + off + (k * 200 + nn) * 2, w2 + (size_t)(kk + k) * 192 + nn);
        }
        cp_commit();
    };
    issueW2(0, 0);
    issueW2(1, 12800);
    __syncthreads();   // hidden complete before reads

    // ---- Phase 4: MLP2 (K=768 from smem hidden, N=192) ----
    float acc2[2][6][4] = {};
    for (int kc = 0; kc < 24; kc++) {
        if (kc < 23) cp_wait<1>(); else cp_wait<0>();
        __syncthreads();
        uint32_t off = (kc & 1) * 12800;
#pragma unroll
        for (int kb2 = 0; kb2 < 32; kb2 += 16) {
            int kb = kc * 32 + kb2;
            uint32_t a[2][4];
#pragma unroll
            for (int mi = 0; mi < 2; mi++)
                ldm_x4(a[mi][0], a[mi][1], a[mi][2], a[mi][3],
                       sH + ((wm * 32 + mi * 16 + l15) * H_STR + kb + (lane >> 4) * 8) * 2);
            uint32_t bfr[6][2];
#pragma unroll
            for (int ni = 0; ni < 6; ni++)
                ldm_x2t(bfr[ni][0], bfr[ni][1],
                        sB + off + ((kb2 + l15) * 200 + wn * 48 + ni * 8) * 2);
#pragma unroll
            for (int mi = 0; mi < 2; mi++)
#pragma unroll
                for (int ni = 0; ni < 6; ni++)
                    mma_bf16(acc2[mi][ni][0], acc2[mi][ni][1], acc2[mi][ni][2], acc2[mi][ni][3],
                             a[mi][0], a[mi][1], a[mi][2], a[mi][3],
                             bfr[ni][0], bfr[ni][1]);
        }
        __syncthreads();
        if (kc + 2 < 24) issueW2(kc + 2, off);
    }

    // epilogue: out += mlp2 + b2
#pragma unroll
    for (int mi = 0; mi < 2; mi++) {
#pragma unroll
        for (int ni = 0; ni < 6; ni++) {
            int colg = wn * 48 + ni * 8 + tig * 2;
            float ob0 = __ldg(b2 + colg), ob1 = __ldg(b2 + colg + 1);
#pragma unroll
            for (int hh = 0; hh < 2; hh++) {
                int row = wm * 32 + mi * 16 + gid + hh * 8;
                int yr = maprow(m0 + row);
                float2 pr = *reinterpret_cast<float2*>(out + (size_t)yr * 192 + colg);
                pr.x += acc2[mi][ni][hh * 2] + ob0;
                pr.y += acc2[mi][ni][hh * 2 + 1] + ob1;
                *reinterpret_cast<float2*>(out + (size_t)yr * 192 + colg) = pr;
            }
        }
    }
}

// ================= tensor-core windowed attention (unchanged) =================
constexpr int SQ = 584;
constexpr int ATT_Q_BYTES = 64 * SQ * 2;
constexpr int ATT_SMEM = ATT_Q_BYTES + 1014 * 4 + 256;

__global__ void __launch_bounds__(384, 1) attn_kernel(const __nv_bfloat16* __restrict__ qkv,
                                                      const float* __restrict__ rpb,
                                                      __nv_bfloat16* __restrict__ outb) {
    extern __shared__ __align__(16) unsigned char smraw[];
    __nv_bfloat16* qkvs = reinterpret_cast<__nv_bfloat16*>(smraw);
    float* rpbh = reinterpret_cast<float*>(smraw + ATT_Q_BYTES);
    int* rid = reinterpret_cast<int*>(smraw + ATT_Q_BYTES + 1014 * 4);
    const uint32_t sQ = (uint32_t)__cvta_generic_to_shared(qkvs);

    const int w = blockIdx.x;
    const int tid = threadIdx.x;

    for (int idx = tid; idx < 15 * SQ / 2; idx += 384)
        reinterpret_cast<uint32_t*>(qkvs)[49 * SQ / 2 + idx] = 0;
    const __nv_bfloat16* src = qkv + (size_t)w * 49 * 576;
#pragma unroll
    for (int i = 0; i < 10; i++) {
        int idx = tid + 384 * i;
        if (idx < 3528) {
            int r = idx / 72, c8 = (idx % 72) * 8;
            cp16(sQ + (r * SQ + c8) * 2, src + (size_t)r * 576 + c8);
        }
    }
    cp_commit();
    for (int idx = tid; idx < 1014; idx += 384) {
        int h = idx / 169, p2 = idx - h * 169;
        rpbh[idx] = rpb[p2 * 6 + h];
    }
    if (tid < 49) {
        int wi = w & 1023;
        int wh = wi >> 5, ww = wi & 31;
        int th = tid / 7, tw = tid - th * 7;
        int hs  = wh * 7 + th;
        int ws2 = ww * 7 + tw;
        int hr = hs  < 217 ? 0 : (hs  < 221 ? 1 : 2);
        int wr = ws2 < 217 ? 0 : (ws2 < 221 ? 1 : 2);
        rid[tid] = hr * 3 + wr;
    }
    cp_wait<0>();
    __syncthreads();

    const int warp = tid >> 5, lane = tid & 31;
    const int h = warp >> 1, mh = warp & 1;
    const int gid = lane >> 2, tig = lane & 3;
    const int l15 = lane & 15;
    const int co = h * 32;

    uint32_t aQ[2][2][4];
#pragma unroll
    for (int mi = 0; mi < 2; mi++)
#pragma unroll
        for (int kt = 0; kt < 2; kt++)
            ldm_x4(aQ[mi][kt][0], aQ[mi][kt][1], aQ[mi][kt][2], aQ[mi][kt][3],
                   sQ + ((mh * 32 + mi * 16 + l15) * SQ + co + kt * 16 + (lane >> 4) * 8) * 2);

    float sacc[2][8][4] = {};
#pragma unroll
    for (int kt = 0; kt < 2; kt++) {
        uint32_t bK[8][2];
#pragma unroll
        for (int ni = 0; ni < 8; ni++)
            ldm_x2(bK[ni][0], bK[ni][1],
                   sQ + ((ni * 8 + (l15 & 7)) * SQ + 192 + co + kt * 16 + ((l15 >> 3) & 1) * 8) * 2);
#pragma unroll
        for (int mi = 0; mi < 2; mi++)
#pragma unroll
            for (int ni = 0; ni < 8; ni++)
                mma_bf16(sacc[mi][ni][0], sacc[mi][ni][1], sacc[mi][ni][2], sacc[mi][ni][3],
                         aQ[mi][kt][0], aQ[mi][kt][1], aQ[mi][kt][2], aQ[mi][kt][3],
                         bK[ni][0], bK[ni][1]);
    }

    const float scale = 0.17677669529663687f;
    const float* rp = rpbh + h * 169;
    uint32_t aP[2][4][4];
#pragma unroll
    for (int mi = 0; mi < 2; mi++) {
        int i0 = mh * 32 + mi * 16 + gid;
        int i1 = i0 + 8;
        int ii0 = min(i0, 48), ii1 = min(i1, 48);
        int ih0 = ii0 / 7, iw0 = ii0 - ih0 * 7;
        int ih1 = ii1 / 7, iw1 = ii1 - ih1 * 7;
        int r0 = rid[ii0], r1 = rid[ii1];
        float mx0 = -1e30f, mx1 = -1e30f;
#pragma unroll
        for (int ni = 0; ni < 8; ni++) {
#pragma unroll
            for (int c = 0; c < 2; c++) {
                int j = ni * 8 + tig * 2 + c;
                if (j < 49) {
                    int jh = j / 7, jw = j - jh * 7;
                    int rj = rid[j];
                    float b0 = rp[(ih0 - jh + 6) * 13 + (iw0 - jw + 6)];
                    float b1 = rp[(ih1 - jh + 6) * 13 + (iw1 - jw + 6)];
                    float s0 = sacc[mi][ni][c] * scale + b0 + (r0 != rj ? -100.f : 0.f);
                    float s1 = sacc[mi][ni][2 + c] * scale + b1 + (r1 != rj ? -100.f : 0.f);
                    sacc[mi][ni][c] = s0;
                    sacc[mi][ni][2 + c] = s1;
                    mx0 = fmaxf(mx0, s0);
                    mx1 = fmaxf(mx1, s1);
                } else {
                    sacc[mi][ni][c] = -1e30f;
                    sacc[mi][ni][2 + c] = -1e30f;
                }
            }
        }
        mx0 = fmaxf(mx0, __shfl_xor_sync(0xffffffffu, mx0, 1));
        mx0 = fmaxf(mx0, __shfl_xor_sync(0xffffffffu, mx0, 2));
        mx1 = fmaxf(mx1, __shfl_xor_sync(0xffffffffu, mx1, 1));
        mx1 = fmaxf(mx1, __shfl_xor_sync(0xffffffffu, mx1, 2));
        float sm0 = 0.f, sm1 = 0.f;
#pragma unroll
        for (int ni = 0; ni < 8; ni++) {
#pragma unroll
            for (int c = 0; c < 2; c++) {
                float e0 = __expf(sacc[mi][ni][c] - mx0);
                float e1 = __expf(sacc[mi][ni][2 + c] - mx1);
                sacc[mi][ni][c] = e0;
                sacc[mi][ni][2 + c] = e1;
                sm0 += e0; sm1 += e1;
            }
        }
        sm0 += __shfl_xor_sync(0xffffffffu, sm0, 1);
        sm0 += __shfl_xor_sync(0xffffffffu, sm0, 2);
        sm1 += __shfl_xor_sync(0xffffffffu, sm1, 1);
        sm1 += __shfl_xor_sync(0xffffffffu, sm1, 2);
        float inv0 = 1.f / sm0, inv1 = 1.f / sm1;
#pragma unroll
        for (int kt = 0; kt < 4; kt++) {
            aP[mi][kt][0] = packbf(sacc[mi][2 * kt][0] * inv0,     sacc[mi][2 * kt][1] * inv0);
            aP[mi][kt][1] = packbf(sacc[mi][2 * kt][2] * inv1,     sacc[mi][2 * kt][3] * inv1);
            aP[mi][kt][2] = packbf(sacc[mi][2 * kt + 1][0] * inv0, sacc[mi][2 * kt + 1][1] * inv0);
            aP[mi][kt][3] = packbf(sacc[mi][2 * kt + 1][2] * inv1, sacc[mi][2 * kt + 1][3] * inv1);
        }
    }

    float oacc[2][4][4] = {};
#pragma unroll
    for (int kt = 0; kt < 4; kt++) {
        uint32_t bV[4][2];
#pragma unroll
        for (int ni = 0; ni < 4; ni++)
            ldm_x2t(bV[ni][0], bV[ni][1],
                    sQ + ((kt * 16 + l15) * SQ + 384 + co + ni * 8) * 2);
#pragma unroll
        for (int mi = 0; mi < 2; mi++)
#pragma unroll
            for (int ni = 0; ni < 4; ni++)
                mma_bf16(oacc[mi][ni][0], oacc[mi][ni][1], oacc[mi][ni][2], oacc[mi][ni][3],
                         aP[mi][kt][0], aP[mi][kt][1], aP[mi][kt][2], aP[mi][kt][3],
                         bV[ni][0], bV[ni][1]);
    }

#pragma unroll
    for (int mi = 0; mi < 2; mi++) {
        int i0 = mh * 32 + mi * 16 + gid;
        if (i0 < 49) {
            __nv_bfloat16* op = outb + (size_t)(w * 49 + i0) * 192 + co;
#pragma unroll
            for (int ni = 0; ni < 4; ni++) {
                uint32_t pk = packbf(oacc[mi][ni][0], oacc[mi][ni][1]);
                *reinterpret_cast<uint32_t*>(op + ni * 8 + tig * 2) = pk;
            }
        }
        int i1 = i0 + 8;
        if (i1 < 49) {
            __nv_bfloat16* op = outb + (size_t)(w * 49 + i1) * 192 + co;
#pragma unroll
            for (int ni = 0; ni < 4; ni++) {
                uint32_t pk = packbf(oacc[mi][ni][2], oacc[mi][ni][3]);
                *reinterpret_cast<uint32_t*>(op + ni * 8 + tig * 2) = pk;
            }
        }
    }
}

// ---------------- launch ----------------
extern "C" void kernel_launch(void* const* d_in, const int* in_sizes, int n_in,
                              void* d_out, int out_size) {
    const float* x      = (const float*)d_in[0];
    const float* qkv_w  = (const float*)d_in[3];
    const float* qkv_b  = (const float*)d_in[4];
    const float* proj_w = (const float*)d_in[5];
    const float* proj_b = (const float*)d_in[6];
    const float* rpb    = (const float*)d_in[7];
    const float* n1w    = (const float*)d_in[8];
    const float* n1b    = (const float*)d_in[9];
    const float* n2w    = (const float*)d_in[10];
    const float* n2b    = (const float*)d_in[11];
    const float* w1     = (const float*)d_in[12];
    const float* b1     = (const float*)d_in[13];
    const float* w2     = (const float*)d_in[14];
    const float* b2     = (const float*)d_in[15];
    float* out = (float*)d_out;

    void* p;
    cudaGetSymbolAddress(&p, g_qkv);   __nv_bfloat16* qkvb  = (__nv_bfloat16*)p;
    cudaGetSymbolAddress(&p, g_attn);  __nv_bfloat16* attnb = (__nv_bfloat16*)p;
    cudaGetSymbolAddress(&p, g_wqkv);  __nv_bfloat16* wqkv  = (__nv_bfloat16*)p;
    cudaGetSymbolAddress(&p, g_wproj); __nv_bfloat16* wproj = (__nv_bfloat16*)p;
    cudaGetSymbolAddress(&p, g_w1);    __nv_bfloat16* w1b   = (__nv_bfloat16*)p;
    cudaGetSymbolAddress(&p, g_w2);    __nv_bfloat16* w2b   = (__nv_bfloat16*)p;

    cudaFuncSetAttribute(gemmQKV_kernel,
                         cudaFuncAttributeMaxDynamicSharedMemorySize, SMEM_QKV);
    cudaFuncSetAttribute(mega_kernel,
                         cudaFuncAttributeMaxDynamicSharedMemorySize, MG_SMEM);
    cudaFuncSetAttribute(attn_kernel,
                         cudaFuncAttributeMaxDynamicSharedMemorySize, ATT_SMEM);

    // weight casts (tiny)
    convert_kernel<<<(192 * 576 + 255) / 256, 256>>>(qkv_w, wqkv, 192 * 576);
    convert_kernel<<<(192 * 192 + 255) / 256, 256>>>(proj_w, wproj, 192 * 192);
    convert_kernel<<<(192 * 768 + 255) / 256, 256>>>(w1, w1b, 192 * 768);
    convert_kernel<<<(768 * 192 + 255) / 256, 256>>>(w2, w2b, 768 * 192);

    // 1) fused LN1 + QKV GEMM
    gemmQKV_kernel<<<T_TOK / 128, 256, SMEM_QKV>>>(x, n1w, n1b, wqkv, qkv_b, qkvb);

    // 2) tensor-core windowed attention
    attn_kernel<<<T_TOK / 49, 384, ATT_SMEM>>>(qkvb, rpb, attnb);

    // 3) proj + resid + LN2 + MLP1(GELU) + MLP2 + resid, hidden never leaves smem
    mega_kernel<<<T_TOK / 64, 256, MG_SMEM>>>(attnb, wproj, proj_b, x, n2w, n2b,
                                              w1b, b1, w2b, b2, out);

    (void)in_sizes; (void)n_in; (void)out_size;
}